// round 9
// baseline (speedup 1.0000x reference)
#include <cuda_runtime.h>
#include <stdint.h>

// EdgeNetwork via register-fragment bf16 mma.sync + cp.async pipelined gather.
//
//   B'[n][k], n in [0,544): n<512 -> B'[n][k] = Kmat[n*32+k]   (reshape(K,512,32))
//                           n>=512 -> bias[(n-512)*32+k]       (reshape(bias,32,32))
//   Per edge e: y[e,i] = sum_{blk=0..16} w[e,blk] * sum_j nb[e,j] * B'[blk*32+i][j]
//   w[e,blk] = bond[e,blk] (blk<16), 1.0 (blk=16, bias block).
//   out = segment_sum(y, src)
//
// Precision: bf16 split, C = Ahi Bhi + Alo Bhi + Ahi Blo (rel err ~1.4e-5, validated).
// Pipeline: per-warp double-buffered neighbor tile filled by cp.async for tile t+1
// while tile t runs its MMA loop; pair indices pipelined 2 deep; bond prefetched
// into registers (bdsh single-buffered, rewritten after the merge loop).

#define NTH    384
#define NWARPS 12
#define GRID_X 148
#define NBLK   17

#define BF_BYTES  (NBLK * 4 * 4 * 32 * 8)   // 69632: Bfrag[blk][n8][v][lane] uint2
#define NB_STRIDE 36                        // f32 row stride (144B, 16B-aligned rows)
#define NB_BYTES  (32 * NB_STRIDE * 4)      // 4608 (one buffer)
#define BD_STRIDE 20                        // f32 row stride (80B rows)
#define BD_BYTES  (32 * BD_STRIDE * 4)      // 2560
#define DST_BYTES 128
#define WARP_BYTES (2 * NB_BYTES + BD_BYTES + 2 * DST_BYTES)       // 12032
#define SMEM_BYTES (BF_BYTES + NWARPS * WARP_BYTES)                // 214016

__device__ __forceinline__ uint32_t prmt7632(uint32_t a, uint32_t b) {
    uint32_t r;
    asm("prmt.b32 %0, %1, %2, 0x7632;" : "=r"(r) : "r"(a), "r"(b));
    return r;
}
__device__ __forceinline__ uint32_t pack_bf16x2(float upper, float lower) {
    uint32_t r;
    asm("cvt.rn.bf16x2.f32 %0, %1, %2;" : "=r"(r) : "f"(upper), "f"(lower));
    return r;
}
__device__ __forceinline__ uint32_t s2u(const void* p) {
    uint32_t a;
    asm("{ .reg .u64 t; cvta.to.shared.u64 t, %1; cvt.u32.u64 %0, t; }" : "=r"(a) : "l"(p));
    return a;
}
__device__ __forceinline__ void cp16(uint32_t dst, const void* src) {
    asm volatile("cp.async.cg.shared.global [%0], [%1], 16;" :: "r"(dst), "l"(src) : "memory");
}
#define CP_COMMIT() asm volatile("cp.async.commit_group;" ::: "memory")
#define CP_WAIT1()  asm volatile("cp.async.wait_group 1;" ::: "memory")

#define MMA16816(c0, c1, c2, c3, a0, a1, a2, a3, b0, b1)                        \
    asm volatile(                                                               \
        "mma.sync.aligned.m16n8k16.row.col.f32.bf16.bf16.f32 "                  \
        "{%0,%1,%2,%3}, {%4,%5,%6,%7}, {%8,%9}, {%0,%1,%2,%3};"                 \
        : "+f"(c0), "+f"(c1), "+f"(c2), "+f"(c3)                                \
        : "r"(a0), "r"(a1), "r"(a2), "r"(a3), "r"(b0), "r"(b1))

__global__ __launch_bounds__(NTH)
void edge_network_hmma(const float* __restrict__ atom,
                       const float* __restrict__ bond,
                       const int* __restrict__ pair,
                       const float* __restrict__ Kmat,
                       const float* __restrict__ bias,
                       float* __restrict__ out,
                       int n_edges, int n_wtiles)
{
    extern __shared__ __align__(16) char smem[];
    const int tid = threadIdx.x;
    const int w = tid >> 5, lane = tid & 31;

    // ---- one-time: B fragment table in m16n8k16 B-operand order ----
    for (int idx = tid; idx < NBLK * 512; idx += NTH) {
        int li  = idx & 31;
        int v   = (idx >> 5) & 3;
        int n8  = (idx >> 7) & 3;
        int blk = idx >> 9;
        int n   = blk * 32 + n8 * 8 + (li >> 2);
        int kb  = (v & 1) * 16 + (li & 3) * 2;
        const float* src = (n < 512) ? (Kmat + n * 32) : (bias + (n - 512) * 32);
        float f0 = src[kb], f1 = src[kb + 1], f2 = src[kb + 8], f3 = src[kb + 9];
        uint2 r;
        if ((v >> 1) == 0) {
            r.x = prmt7632(__float_as_uint(f0), __float_as_uint(f1));
            r.y = prmt7632(__float_as_uint(f2), __float_as_uint(f3));
        } else {
            float l0 = f0 - __uint_as_float(__float_as_uint(f0) & 0xFFFF0000u);
            float l1 = f1 - __uint_as_float(__float_as_uint(f1) & 0xFFFF0000u);
            float l2 = f2 - __uint_as_float(__float_as_uint(f2) & 0xFFFF0000u);
            float l3 = f3 - __uint_as_float(__float_as_uint(f3) & 0xFFFF0000u);
            r.x = pack_bf16x2(l1, l0);
            r.y = pack_bf16x2(l3, l2);
        }
        reinterpret_cast<uint2*>(smem)[idx] = r;
    }
    __syncthreads();

    char* wbase = smem + BF_BYTES + w * WARP_BYTES;
    float* nbbuf[2] = { (float*)wbase, (float*)(wbase + NB_BYTES) };
    float* bdsh = (float*)(wbase + 2 * NB_BYTES);
    int*   dstb[2] = { (int*)(wbase + 2 * NB_BYTES + BD_BYTES),
                       (int*)(wbase + 2 * NB_BYTES + BD_BYTES + DST_BYTES) };
    uint32_t nb_u32[2] = { s2u(nbbuf[0]), s2u(nbbuf[1]) };
    const uint2* bft = reinterpret_cast<const uint2*>(smem);

    const int warp_gid = blockIdx.x * NWARPS + w;
    const int wstep    = gridDim.x * NWARPS;

    if (warp_gid < n_wtiles) {
        int t = warp_gid;
        const int emax = n_edges - 1;

        // ---- prologue: pair(t), cp.async nb(t)->buf0, pair(t+step), bond(t) ----
        int e0l = t * 32 + lane;
        int ec  = e0l < n_edges ? e0l : emax;
        int2 pA = reinterpret_cast<const int2*>(pair)[ec];
        {
            uint32_t d = nb_u32[0] + lane * (NB_STRIDE * 4);
            const char* s = (const char*)(atom + (size_t)pA.y * 32);
            #pragma unroll
            for (int q = 0; q < 8; q++) cp16(d + q * 16, s + q * 16);
        }
        CP_COMMIT();
        int t1 = t + wstep;
        int e1l = t1 * 32 + lane;
        int e1c = e1l < n_edges ? e1l : emax;
        int2 pB = reinterpret_cast<const int2*>(pair)[(t1 < n_wtiles) ? e1c : ec];
        // bond(t) -> bdsh + dst(buf0)
        {
            const float4* bsrc = reinterpret_cast<const float4*>(bond + (size_t)ec * 16);
            float4 b0 = bsrc[0], b1 = bsrc[1], b2 = bsrc[2], b3 = bsrc[3];
            float4* bd = reinterpret_cast<float4*>(&bdsh[lane * BD_STRIDE]);
            bd[0] = b0; bd[1] = b1; bd[2] = b2; bd[3] = b3;
            bdsh[lane * BD_STRIDE + 16] = 1.0f;
            dstb[0][lane] = (e0l < n_edges) ? pA.x : -1;
        }
        __syncwarp();

        int cur = 0;
        while (t < n_wtiles) {
            const int tn = t + wstep;

            // ---- issue cp.async for tile tn into the other buffer ----
            if (tn < n_wtiles) {
                uint32_t d = nb_u32[cur ^ 1] + lane * (NB_STRIDE * 4);
                const char* s = (const char*)(atom + (size_t)pB.y * 32);
                #pragma unroll
                for (int q = 0; q < 8; q++) cp16(d + q * 16, s + q * 16);
            }
            CP_COMMIT();

            // ---- prefetch pair(t+2*step) and bond(tn) into registers ----
            int t2 = tn + wstep;
            int e2l = t2 * 32 + lane;
            int e2c = e2l < n_edges ? e2l : emax;
            int2 pC = reinterpret_cast<const int2*>(pair)[(t2 < n_wtiles) ? e2c : 0];
            float4 nb0, nb1, nb2, nb3;
            int enl = tn * 32 + lane;
            int enc = enl < n_edges ? enl : emax;
            if (tn < n_wtiles) {
                const float4* bsrc = reinterpret_cast<const float4*>(bond + (size_t)enc * 16);
                nb0 = bsrc[0]; nb1 = bsrc[1]; nb2 = bsrc[2]; nb3 = bsrc[3];
            }

            // ---- wait for current tile's neighbor data ----
            CP_WAIT1();
            __syncwarp();

            float* nbsh = nbbuf[cur];

            // ---- build A fragments (hi/lo bf16 split) ----
            uint32_t ahi[2][8], alo[2][8];
            #pragma unroll
            for (int g = 0; g < 2; g++)
                #pragma unroll
                for (int kc = 0; kc < 2; kc++)
                    #pragma unroll
                    for (int q = 0; q < 4; q++) {
                        int r = g * 16 + (lane >> 2) + (q & 1) * 8;
                        int c = kc * 16 + (lane & 3) * 2 + (q >> 1) * 8;
                        float2 f = *reinterpret_cast<const float2*>(&nbsh[r * NB_STRIDE + c]);
                        uint32_t u0 = __float_as_uint(f.x), u1 = __float_as_uint(f.y);
                        float l0 = f.x - __uint_as_float(u0 & 0xFFFF0000u);
                        float l1 = f.y - __uint_as_float(u1 & 0xFFFF0000u);
                        ahi[g][kc * 4 + q] = prmt7632(u0, u1);
                        alo[g][kc * 4 + q] = pack_bf16x2(l1, l0);
                    }
            __syncwarp();  // done reading nbsh; reusable for y

            float yac[2][16];
            #pragma unroll
            for (int g = 0; g < 2; g++)
                #pragma unroll
                for (int i = 0; i < 16; i++) yac[g][i] = 0.f;

            // ---- 17 column-blocks: 48 MMAs + bond-weighted merge each ----
            #pragma unroll 1
            for (int blk = 0; blk < NBLK; blk++) {
                float w00 = bdsh[((lane >> 2) + 0)  * BD_STRIDE + blk];
                float w01 = bdsh[((lane >> 2) + 8)  * BD_STRIDE + blk];
                float w10 = bdsh[((lane >> 2) + 16) * BD_STRIDE + blk];
                float w11 = bdsh[((lane >> 2) + 24) * BD_STRIDE + blk];
                #pragma unroll
                for (int n8 = 0; n8 < 4; n8++) {
                    const uint2* bp = bft + ((blk * 4 + n8) * 4) * 32 + lane;
                    uint2 v0 = bp[0], v1 = bp[32], v2 = bp[64], v3 = bp[96];
                    #pragma unroll
                    for (int g = 0; g < 2; g++) {
                        float c0 = 0.f, c1 = 0.f, c2 = 0.f, c3 = 0.f;
                        MMA16816(c0, c1, c2, c3, ahi[g][0], ahi[g][1], ahi[g][2], ahi[g][3], v0.x, v0.y);
                        MMA16816(c0, c1, c2, c3, ahi[g][4], ahi[g][5], ahi[g][6], ahi[g][7], v1.x, v1.y);
                        MMA16816(c0, c1, c2, c3, alo[g][0], alo[g][1], alo[g][2], alo[g][3], v0.x, v0.y);
                        MMA16816(c0, c1, c2, c3, alo[g][4], alo[g][5], alo[g][6], alo[g][7], v1.x, v1.y);
                        MMA16816(c0, c1, c2, c3, ahi[g][0], ahi[g][1], ahi[g][2], ahi[g][3], v2.x, v2.y);
                        MMA16816(c0, c1, c2, c3, ahi[g][4], ahi[g][5], ahi[g][6], ahi[g][7], v3.x, v3.y);
                        float wa = g ? w10 : w00;
                        float wb = g ? w11 : w01;
                        yac[g][n8 * 4 + 0] = fmaf(wa, c0, yac[g][n8 * 4 + 0]);
                        yac[g][n8 * 4 + 1] = fmaf(wa, c1, yac[g][n8 * 4 + 1]);
                        yac[g][n8 * 4 + 2] = fmaf(wb, c2, yac[g][n8 * 4 + 2]);
                        yac[g][n8 * 4 + 3] = fmaf(wb, c3, yac[g][n8 * 4 + 3]);
                    }
                }
            }
            __syncwarp();  // merge done reading bdsh

            // ---- install next tile's bond weights + dst ----
            if (tn < n_wtiles) {
                float4* bd = reinterpret_cast<float4*>(&bdsh[lane * BD_STRIDE]);
                bd[0] = nb0; bd[1] = nb1; bd[2] = nb2; bd[3] = nb3;
                dstb[cur ^ 1][lane] = (enl < n_edges) ? pB.x : -1;
            }

            // ---- y fragments -> nbsh (reused), then vector red scatter ----
            #pragma unroll
            for (int g = 0; g < 2; g++)
                #pragma unroll
                for (int n8 = 0; n8 < 4; n8++) {
                    int r0 = g * 16 + (lane >> 2);
                    int c  = n8 * 8 + (lane & 3) * 2;
                    *reinterpret_cast<float2*>(&nbsh[r0 * NB_STRIDE + c]) =
                        make_float2(yac[g][n8 * 4 + 0], yac[g][n8 * 4 + 1]);
                    *reinterpret_cast<float2*>(&nbsh[(r0 + 8) * NB_STRIDE + c]) =
                        make_float2(yac[g][n8 * 4 + 2], yac[g][n8 * 4 + 3]);
                }
            __syncwarp();

            const int* dstw = dstb[cur];
            #pragma unroll 1
            for (int rr = 0; rr < 8; rr++) {
                int el = rr * 4 + (lane >> 3);
                int c  = (lane & 7) * 4;
                int d  = dstw[el];
                if (d >= 0) {
                    float4 v = *reinterpret_cast<const float4*>(&nbsh[el * NB_STRIDE + c]);
                    asm volatile("red.global.add.v4.f32 [%0], {%1,%2,%3,%4};"
                                 :: "l"(out + (size_t)d * 32 + c),
                                    "f"(v.x), "f"(v.y), "f"(v.z), "f"(v.w)
                                 : "memory");
                }
            }
            __syncwarp();  // nbsh reads done before it becomes a cp.async target

            pB = pC;
            t = tn;
            cur ^= 1;
        }
    }
}

extern "C" void kernel_launch(void* const* d_in, const int* in_sizes, int n_in,
                              void* d_out, int out_size) {
    const float* atom = (const float*)d_in[0];
    const float* bond = (const float*)d_in[1];
    const int*   pair = (const int*)d_in[2];
    const float* Kmat = (const float*)d_in[3];
    const float* bias = (const float*)d_in[4];
    float*       out  = (float*)d_out;

    const int n_edges  = in_sizes[1] / 16;
    const int n_wtiles = (n_edges + 31) / 32;

    cudaFuncSetAttribute(edge_network_hmma,
                         cudaFuncAttributeMaxDynamicSharedMemorySize, SMEM_BYTES);

    cudaMemsetAsync(d_out, 0, (size_t)out_size * sizeof(float), 0);

    int nblocks = (n_wtiles + NWARPS - 1) / NWARPS;
    if (nblocks > GRID_X) nblocks = GRID_X;
    edge_network_hmma<<<nblocks, NTH, SMEM_BYTES>>>(atom, bond, pair, Kmat, bias, out,
                                                    n_edges, n_wtiles);
}

// round 11
// speedup vs baseline: 1.0227x; 1.0227x over previous
#include <cuda_runtime.h>
#include <stdint.h>

// EdgeNetwork via register-fragment bf16 mma.sync + dynamic work stealing.
//
//   B'[n][k], n in [0,544): n<512 -> B'[n][k] = Kmat[n*32+k]   (reshape(K,512,32))
//                           n>=512 -> bias[(n-512)*32+k]       (reshape(bias,32,32))
//   Per edge e: y[e,i] = sum_{blk=0..16} w[e,blk] * sum_j nb[e,j] * B'[blk*32+i][j]
//   w[e,blk] = bond[e,blk] (blk<16), 1.0 (blk=16, bias block).
//   out = segment_sum(y, src)
//
// Precision: bf16 split, C = Ahi Bhi + Alo Bhi + Ahi Blo (rel err ~1.4e-5, validated).
// R10: + global-atomic tile stealing (kills the 13.7% static-stride tail imbalance),
//      + per-group MMA chain split (2 independent 3-chains instead of one 6-chain).

#define NTH    512
#define NWARPS 16
#define GRID_X 148
#define NBLK   17

#define BF_BYTES  (NBLK * 4 * 4 * 32 * 8)   // 69632: Bfrag[blk][n8][v][lane] uint2
#define NB_STRIDE 36                        // f32 row stride (144B, 16B-aligned rows)
#define NB_BYTES  (32 * NB_STRIDE * 4)      // 4608 per warp (nb staging, reused for y)
#define BD_STRIDE 20                        // f32 row stride (80B, 16B-aligned rows)
#define BD_BYTES  (32 * BD_STRIDE * 4)      // 2560 per warp
#define DST_BYTES (32 * 4)

#define OFF_NB(wid)  (BF_BYTES + (wid) * NB_BYTES)
#define OFF_BD(wid)  (BF_BYTES + NWARPS * NB_BYTES + (wid) * BD_BYTES)
#define OFF_DS(wid)  (BF_BYTES + NWARPS * (NB_BYTES + BD_BYTES) + (wid) * DST_BYTES)
#define SMEM_BYTES   (BF_BYTES + NWARPS * (NB_BYTES + BD_BYTES + DST_BYTES))  // 186368

__device__ unsigned int g_tile_ctr;

__device__ __forceinline__ uint32_t prmt7632(uint32_t a, uint32_t b) {
    uint32_t r;
    asm("prmt.b32 %0, %1, %2, 0x7632;" : "=r"(r) : "r"(a), "r"(b));
    return r;  // {hi16(b), hi16(a)}: lower half = truncated-bf16(a)
}
__device__ __forceinline__ uint32_t pack_bf16x2(float upper, float lower) {
    uint32_t r;
    asm("cvt.rn.bf16x2.f32 %0, %1, %2;" : "=r"(r) : "f"(upper), "f"(lower));
    return r;
}

#define MMA16816(c0, c1, c2, c3, a0, a1, a2, a3, b0, b1)                        \
    asm volatile(                                                               \
        "mma.sync.aligned.m16n8k16.row.col.f32.bf16.bf16.f32 "                  \
        "{%0,%1,%2,%3}, {%4,%5,%6,%7}, {%8,%9}, {%0,%1,%2,%3};"                 \
        : "+f"(c0), "+f"(c1), "+f"(c2), "+f"(c3)                                \
        : "r"(a0), "r"(a1), "r"(a2), "r"(a3), "r"(b0), "r"(b1))

__global__ __launch_bounds__(NTH)
void edge_network_hmma(const float* __restrict__ atom,
                       const float* __restrict__ bond,
                       const int* __restrict__ pair,
                       const float* __restrict__ Kmat,
                       const float* __restrict__ bias,
                       float* __restrict__ out,
                       int n_edges, int n_wtiles)
{
    extern __shared__ __align__(16) char smem[];
    const int tid = threadIdx.x;
    const int w = tid >> 5, lane = tid & 31;

    // ---- one-time: build B fragment table in exact m16n8k16 B-operand order ----
    // idx = blk*512 + n8*128 + v*32 + lane;  v: 0=hi k0-15, 1=hi k16-31, 2=lo k0-15, 3=lo k16-31
    for (int idx = tid; idx < NBLK * 512; idx += NTH) {
        int li  = idx & 31;
        int v   = (idx >> 5) & 3;
        int n8  = (idx >> 7) & 3;
        int blk = idx >> 9;
        int n   = blk * 32 + n8 * 8 + (li >> 2);
        int kb  = (v & 1) * 16 + (li & 3) * 2;
        const float* src = (n < 512) ? (Kmat + n * 32) : (bias + (n - 512) * 32);
        float f0 = src[kb], f1 = src[kb + 1], f2 = src[kb + 8], f3 = src[kb + 9];
        uint2 r;
        if ((v >> 1) == 0) {  // hi: truncated bf16
            r.x = prmt7632(__float_as_uint(f0), __float_as_uint(f1));
            r.y = prmt7632(__float_as_uint(f2), __float_as_uint(f3));
        } else {              // lo: residual, rn-rounded bf16
            float l0 = f0 - __uint_as_float(__float_as_uint(f0) & 0xFFFF0000u);
            float l1 = f1 - __uint_as_float(__float_as_uint(f1) & 0xFFFF0000u);
            float l2 = f2 - __uint_as_float(__float_as_uint(f2) & 0xFFFF0000u);
            float l3 = f3 - __uint_as_float(__float_as_uint(f3) & 0xFFFF0000u);
            r.x = pack_bf16x2(l1, l0);
            r.y = pack_bf16x2(l3, l2);
        }
        reinterpret_cast<uint2*>(smem)[idx] = r;
    }
    __syncthreads();

    float* nbsh  = (float*)(smem + OFF_NB(w));  // [32][36], reused as y-tile
    float* bdsh  = (float*)(smem + OFF_BD(w));  // [32][20], col 16 = 1.0 (bias weight)
    int*   dstw  = (int*)(smem + OFF_DS(w));
    const uint2* bft = reinterpret_cast<const uint2*>(smem);

    // ---- dynamic work stealing: lane 0 grabs tile indices ----
    int t;
    if (lane == 0) t = (int)atomicAdd(&g_tile_ctr, 1u);
    t = __shfl_sync(0xFFFFFFFFu, t, 0);

    while (t < n_wtiles) {
        // grab next tile now; 318-cyc ATOMG latency hides under this tile's work
        int tn_l0;
        if (lane == 0) tn_l0 = (int)atomicAdd(&g_tile_ctr, 1u);

        const int e0 = t * 32;

        // ---- stage: 32 nb rows (gather) + bond rows; 2 lanes per edge, 2 passes ----
        #pragma unroll
        for (int p = 0; p < 2; p++) {
            int el = p * 16 + (lane >> 1);
            int e  = e0 + el;
            int hf = lane & 1;
            const float4 z = make_float4(0.f, 0.f, 0.f, 0.f);
            const float* asrc = nullptr;
            if (e < n_edges) asrc = atom + (size_t)pair[2 * e + 1] * 32 + hf * 16;
            #pragma unroll
            for (int q = 0; q < 4; q++) {
                float4 vv = asrc ? *reinterpret_cast<const float4*>(asrc + q * 4) : z;
                *reinterpret_cast<float4*>(&nbsh[el * NB_STRIDE + hf * 16 + q * 4]) = vv;
            }
            #pragma unroll
            for (int q = 0; q < 2; q++) {
                float4 vv = (e < n_edges)
                    ? *reinterpret_cast<const float4*>(bond + (size_t)e * 16 + hf * 8 + q * 4) : z;
                *reinterpret_cast<float4*>(&bdsh[el * BD_STRIDE + hf * 8 + q * 4]) = vv;
            }
        }
        {
            int e = e0 + lane;
            dstw[lane] = (e < n_edges) ? pair[2 * e] : -1;
            bdsh[lane * BD_STRIDE + 16] = 1.0f;  // bias-block weight
        }
        __syncwarp();

        // ---- build A fragments (hi/lo bf16 split), 2 row-groups x 2 k-chunks ----
        uint32_t ahi[2][8], alo[2][8];
        #pragma unroll
        for (int g = 0; g < 2; g++)
            #pragma unroll
            for (int kc = 0; kc < 2; kc++)
                #pragma unroll
                for (int q = 0; q < 4; q++) {
                    int r = g * 16 + (lane >> 2) + (q & 1) * 8;
                    int c = kc * 16 + (lane & 3) * 2 + (q >> 1) * 8;
                    float2 f = *reinterpret_cast<const float2*>(&nbsh[r * NB_STRIDE + c]);
                    uint32_t u0 = __float_as_uint(f.x), u1 = __float_as_uint(f.y);
                    float l0 = f.x - __uint_as_float(u0 & 0xFFFF0000u);
                    float l1 = f.y - __uint_as_float(u1 & 0xFFFF0000u);
                    ahi[g][kc * 4 + q] = prmt7632(u0, u1);
                    alo[g][kc * 4 + q] = pack_bf16x2(l1, l0);
                }
        __syncwarp();  // all lanes done reading nbsh; safe to reuse it for y

        float yac[2][16];
        #pragma unroll
        for (int g = 0; g < 2; g++)
            #pragma unroll
            for (int i = 0; i < 16; i++) yac[g][i] = 0.f;

        // ---- main loop: 17 column-blocks; per block 48 MMAs as 2x 3-chains/group ----
        #pragma unroll 1
        for (int blk = 0; blk < NBLK; blk++) {
            float w00 = bdsh[((lane >> 2) + 0)  * BD_STRIDE + blk];
            float w01 = bdsh[((lane >> 2) + 8)  * BD_STRIDE + blk];
            float w10 = bdsh[((lane >> 2) + 16) * BD_STRIDE + blk];
            float w11 = bdsh[((lane >> 2) + 24) * BD_STRIDE + blk];
            #pragma unroll
            for (int n8 = 0; n8 < 4; n8++) {
                const uint2* bp = bft + ((blk * 4 + n8) * 4) * 32 + lane;
                uint2 v0 = bp[0], v1 = bp[32], v2 = bp[64], v3 = bp[96];
                #pragma unroll
                for (int g = 0; g < 2; g++) {
                    // two independent 3-deep chains (halved MMA dependency depth)
                    float a0 = 0.f, a1 = 0.f, a2 = 0.f, a3 = 0.f;
                    float b0 = 0.f, b1 = 0.f, b2 = 0.f, b3 = 0.f;
                    MMA16816(a0, a1, a2, a3, ahi[g][0], ahi[g][1], ahi[g][2], ahi[g][3], v0.x, v0.y);
                    MMA16816(b0, b1, b2, b3, ahi[g][4], ahi[g][5], ahi[g][6], ahi[g][7], v1.x, v1.y);
                    MMA16816(a0, a1, a2, a3, alo[g][0], alo[g][1], alo[g][2], alo[g][3], v0.x, v0.y);
                    MMA16816(b0, b1, b2, b3, alo[g][4], alo[g][5], alo[g][6], alo[g][7], v1.x, v1.y);
                    MMA16816(a0, a1, a2, a3, ahi[g][0], ahi[g][1], ahi[g][2], ahi[g][3], v2.x, v2.y);
                    MMA16816(b0, b1, b2, b3, ahi[g][4], ahi[g][5], ahi[g][6], ahi[g][7], v3.x, v3.y);
                    float wa = g ? w10 : w00;
                    float wb = g ? w11 : w01;
                    yac[g][n8 * 4 + 0] = fmaf(wa, a0, fmaf(wa, b0, yac[g][n8 * 4 + 0]));
                    yac[g][n8 * 4 + 1] = fmaf(wa, a1, fmaf(wa, b1, yac[g][n8 * 4 + 1]));
                    yac[g][n8 * 4 + 2] = fmaf(wb, a2, fmaf(wb, b2, yac[g][n8 * 4 + 2]));
                    yac[g][n8 * 4 + 3] = fmaf(wb, a3, fmaf(wb, b3, yac[g][n8 * 4 + 3]));
                }
            }
        }

        // ---- y fragments -> smem (reuse nbsh) ----
        #pragma unroll
        for (int g = 0; g < 2; g++)
            #pragma unroll
            for (int n8 = 0; n8 < 4; n8++) {
                int r0 = g * 16 + (lane >> 2);
                int c  = n8 * 8 + (lane & 3) * 2;
                *reinterpret_cast<float2*>(&nbsh[r0 * NB_STRIDE + c]) =
                    make_float2(yac[g][n8 * 4 + 0], yac[g][n8 * 4 + 1]);
                *reinterpret_cast<float2*>(&nbsh[(r0 + 8) * NB_STRIDE + c]) =
                    make_float2(yac[g][n8 * 4 + 2], yac[g][n8 * 4 + 3]);
            }
        __syncwarp();

        // ---- scatter-add via vector red: 8 lanes x v4.f32 per edge, 4 edges/iter ----
        #pragma unroll 1
        for (int rr = 0; rr < 8; rr++) {
            int el = rr * 4 + (lane >> 3);
            int c  = (lane & 7) * 4;
            int d  = dstw[el];
            if (d >= 0) {
                float4 v = *reinterpret_cast<const float4*>(&nbsh[el * NB_STRIDE + c]);
                asm volatile("red.global.add.v4.f32 [%0], {%1,%2,%3,%4};"
                             :: "l"(out + (size_t)d * 32 + c),
                                "f"(v.x), "f"(v.y), "f"(v.z), "f"(v.w)
                             : "memory");
            }
        }
        __syncwarp();  // finish reading nbsh before next tile's staging overwrites it

        t = __shfl_sync(0xFFFFFFFFu, tn_l0, 0);
    }
}

extern "C" void kernel_launch(void* const* d_in, const int* in_sizes, int n_in,
                              void* d_out, int out_size) {
    const float* atom = (const float*)d_in[0];
    const float* bond = (const float*)d_in[1];
    const int*   pair = (const int*)d_in[2];
    const float* Kmat = (const float*)d_in[3];
    const float* bias = (const float*)d_in[4];
    float*       out  = (float*)d_out;

    const int n_edges  = in_sizes[1] / 16;
    const int n_wtiles = (n_edges + 31) / 32;

    cudaFuncSetAttribute(edge_network_hmma,
                         cudaFuncAttributeMaxDynamicSharedMemorySize, SMEM_BYTES);

    // reset the work-stealing counter + zero the poisoned output (both capturable)
    void* ctr_addr = nullptr;
    cudaGetSymbolAddress(&ctr_addr, g_tile_ctr);
    cudaMemsetAsync(ctr_addr, 0, sizeof(unsigned int), 0);
    cudaMemsetAsync(d_out, 0, (size_t)out_size * sizeof(float), 0);

    int nblocks = (n_wtiles + NWARPS - 1) / NWARPS;
    if (nblocks > GRID_X) nblocks = GRID_X;
    edge_network_hmma<<<nblocks, NTH, SMEM_BYTES>>>(atom, bond, pair, Kmat, bias, out,
                                                    n_edges, n_wtiles);
}

// round 12
// speedup vs baseline: 1.3772x; 1.3466x over previous
#include <cuda_runtime.h>
#include <cuda_fp16.h>
#include <stdint.h>

// EdgeNetwork via register-fragment fp16 mma.sync, 2-term split + work stealing.
//
//   B'[n][k], n in [0,544): n<512 -> B'[n][k] = Kmat[n*32+k]   (reshape(K,512,32))
//                           n>=512 -> bias[(n-512)*32+k]       (reshape(bias,32,32))
//   Per edge e: y[e,i] = sum_{blk=0..16} w[e,blk] * sum_j nb[e,j] * B'[blk*32+i][j]
//   w[e,blk] = bond[e,blk] (blk<16), 1.0 (blk=16, bias block).
//   out = segment_sum(y, src)
//
// Precision: fp16 2-term split: C = (Ahi + Alo) * Bhi with Ahi=f16(a),
// Alo=f16(a-Ahi), Bhi=f16(b). Residual error ~2^-11 ≈ 4.9e-4 rel (< 1e-3 gate;
// R7 validated the dropped-term error model to ~10%).
// 544 MMAs/tile vs 816 for the bf16 3-pass variant.

#define NTH    512
#define NWARPS 16
#define GRID_X 148
#define NBLK   17

#define BF_BYTES  (NBLK * 4 * 2 * 32 * 8)   // 34816: Bfrag[blk][n8][v][lane] uint2
#define NB_STRIDE 36                        // f32 row stride (144B, 16B-aligned rows)
#define NB_BYTES  (32 * NB_STRIDE * 4)      // 4608 per warp (nb staging, reused for y)
#define BD_STRIDE 20                        // f32 row stride (80B, 16B-aligned rows)
#define BD_BYTES  (32 * BD_STRIDE * 4)      // 2560 per warp
#define DST_BYTES (32 * 4)

#define OFF_NB(wid)  (BF_BYTES + (wid) * NB_BYTES)
#define OFF_BD(wid)  (BF_BYTES + NWARPS * NB_BYTES + (wid) * BD_BYTES)
#define OFF_DS(wid)  (BF_BYTES + NWARPS * (NB_BYTES + BD_BYTES) + (wid) * DST_BYTES)
#define SMEM_BYTES   (BF_BYTES + NWARPS * (NB_BYTES + BD_BYTES + DST_BYTES))  // 151552

__device__ unsigned int g_tile_ctr;

__device__ __forceinline__ uint32_t packh2(__half lo, __half hi) {
    __half2 h = __halves2half2(lo, hi);   // .x = lo half (low 16 bits)
    return *reinterpret_cast<uint32_t*>(&h);
}

#define MMA16816(c0, c1, c2, c3, a0, a1, a2, a3, b0, b1)                        \
    asm volatile(                                                               \
        "mma.sync.aligned.m16n8k16.row.col.f32.f16.f16.f32 "                    \
        "{%0,%1,%2,%3}, {%4,%5,%6,%7}, {%8,%9}, {%0,%1,%2,%3};"                 \
        : "+f"(c0), "+f"(c1), "+f"(c2), "+f"(c3)                                \
        : "r"(a0), "r"(a1), "r"(a2), "r"(a3), "r"(b0), "r"(b1))

__global__ __launch_bounds__(NTH)
void edge_network_hmma(const float* __restrict__ atom,
                       const float* __restrict__ bond,
                       const int* __restrict__ pair,
                       const float* __restrict__ Kmat,
                       const float* __restrict__ bias,
                       float* __restrict__ out,
                       int n_edges, int n_wtiles)
{
    extern __shared__ __align__(16) char smem[];
    const int tid = threadIdx.x;
    const int w = tid >> 5, lane = tid & 31;

    // ---- one-time: build fp16 B fragment table in m16n8k16 B-operand order ----
    // idx = blk*256 + n8*64 + v*32 + lane;  v: 0 = k0-15, 1 = k16-31
    for (int idx = tid; idx < NBLK * 256; idx += NTH) {
        int li  = idx & 31;
        int v   = (idx >> 5) & 1;
        int n8  = (idx >> 6) & 3;
        int blk = idx >> 8;
        int n   = blk * 32 + n8 * 8 + (li >> 2);
        int kb  = v * 16 + (li & 3) * 2;
        const float* src = (n < 512) ? (Kmat + n * 32) : (bias + (n - 512) * 32);
        float f0 = src[kb], f1 = src[kb + 1], f2 = src[kb + 8], f3 = src[kb + 9];
        uint2 r;
        r.x = packh2(__float2half_rn(f0), __float2half_rn(f1));
        r.y = packh2(__float2half_rn(f2), __float2half_rn(f3));
        reinterpret_cast<uint2*>(smem)[idx] = r;
    }
    __syncthreads();

    float* nbsh  = (float*)(smem + OFF_NB(w));  // [32][36], reused as y-tile
    float* bdsh  = (float*)(smem + OFF_BD(w));  // [32][20], col 16 = 1.0 (bias weight)
    int*   dstw  = (int*)(smem + OFF_DS(w));
    const uint2* bft = reinterpret_cast<const uint2*>(smem);

    // ---- dynamic work stealing: lane 0 grabs tile indices ----
    int t;
    if (lane == 0) t = (int)atomicAdd(&g_tile_ctr, 1u);
    t = __shfl_sync(0xFFFFFFFFu, t, 0);

    while (t < n_wtiles) {
        int tn_l0;  // grab next tile now; ATOMG latency hides under this tile's work
        if (lane == 0) tn_l0 = (int)atomicAdd(&g_tile_ctr, 1u);

        const int e0 = t * 32;

        // ---- stage: 32 nb rows (gather) + bond rows; 2 lanes per edge, 2 passes ----
        #pragma unroll
        for (int p = 0; p < 2; p++) {
            int el = p * 16 + (lane >> 1);
            int e  = e0 + el;
            int hf = lane & 1;
            const float4 z = make_float4(0.f, 0.f, 0.f, 0.f);
            const float* asrc = nullptr;
            if (e < n_edges) asrc = atom + (size_t)pair[2 * e + 1] * 32 + hf * 16;
            #pragma unroll
            for (int q = 0; q < 4; q++) {
                float4 vv = asrc ? *reinterpret_cast<const float4*>(asrc + q * 4) : z;
                *reinterpret_cast<float4*>(&nbsh[el * NB_STRIDE + hf * 16 + q * 4]) = vv;
            }
            #pragma unroll
            for (int q = 0; q < 2; q++) {
                float4 vv = (e < n_edges)
                    ? *reinterpret_cast<const float4*>(bond + (size_t)e * 16 + hf * 8 + q * 4) : z;
                *reinterpret_cast<float4*>(&bdsh[el * BD_STRIDE + hf * 8 + q * 4]) = vv;
            }
        }
        {
            int e = e0 + lane;
            dstw[lane] = (e < n_edges) ? pair[2 * e] : -1;
            bdsh[lane * BD_STRIDE + 16] = 1.0f;  // bias-block weight
        }
        __syncwarp();

        // ---- build A fragments (fp16 hi + fp16 residual lo) ----
        uint32_t ahi[2][8], alo[2][8];
        #pragma unroll
        for (int g = 0; g < 2; g++)
            #pragma unroll
            for (int kc = 0; kc < 2; kc++)
                #pragma unroll
                for (int q = 0; q < 4; q++) {
                    int r = g * 16 + (lane >> 2) + (q & 1) * 8;
                    int c = kc * 16 + (lane & 3) * 2 + (q >> 1) * 8;
                    float2 f = *reinterpret_cast<const float2*>(&nbsh[r * NB_STRIDE + c]);
                    __half hx = __float2half_rn(f.x), hy = __float2half_rn(f.y);
                    __half lx = __float2half_rn(f.x - __half2float(hx));
                    __half ly = __float2half_rn(f.y - __half2float(hy));
                    ahi[g][kc * 4 + q] = packh2(hx, hy);
                    alo[g][kc * 4 + q] = packh2(lx, ly);
                }
        __syncwarp();  // all lanes done reading nbsh; safe to reuse it for y

        float yac[2][16];
        #pragma unroll
        for (int g = 0; g < 2; g++)
            #pragma unroll
            for (int i = 0; i < 16; i++) yac[g][i] = 0.f;

        // ---- main loop: 17 column-blocks; per block 32 MMAs as 2x depth-2 chains ----
        #pragma unroll 1
        for (int blk = 0; blk < NBLK; blk++) {
            float w00 = bdsh[((lane >> 2) + 0)  * BD_STRIDE + blk];
            float w01 = bdsh[((lane >> 2) + 8)  * BD_STRIDE + blk];
            float w10 = bdsh[((lane >> 2) + 16) * BD_STRIDE + blk];
            float w11 = bdsh[((lane >> 2) + 24) * BD_STRIDE + blk];
            #pragma unroll
            for (int n8 = 0; n8 < 4; n8++) {
                const uint2* bp = bft + ((blk * 4 + n8) * 2) * 32 + lane;
                uint2 v0 = bp[0], v1 = bp[32];
                #pragma unroll
                for (int g = 0; g < 2; g++) {
                    // two independent depth-2 chains (k-chunk 0 and 1)
                    float a0 = 0.f, a1 = 0.f, a2 = 0.f, a3 = 0.f;
                    float b0 = 0.f, b1 = 0.f, b2 = 0.f, b3 = 0.f;
                    MMA16816(a0, a1, a2, a3, ahi[g][0], ahi[g][1], ahi[g][2], ahi[g][3], v0.x, v0.y);
                    MMA16816(b0, b1, b2, b3, ahi[g][4], ahi[g][5], ahi[g][6], ahi[g][7], v1.x, v1.y);
                    MMA16816(a0, a1, a2, a3, alo[g][0], alo[g][1], alo[g][2], alo[g][3], v0.x, v0.y);
                    MMA16816(b0, b1, b2, b3, alo[g][4], alo[g][5], alo[g][6], alo[g][7], v1.x, v1.y);
                    float wa = g ? w10 : w00;
                    float wb = g ? w11 : w01;
                    yac[g][n8 * 4 + 0] = fmaf(wa, a0 + b0, yac[g][n8 * 4 + 0]);
                    yac[g][n8 * 4 + 1] = fmaf(wa, a1 + b1, yac[g][n8 * 4 + 1]);
                    yac[g][n8 * 4 + 2] = fmaf(wb, a2 + b2, yac[g][n8 * 4 + 2]);
                    yac[g][n8 * 4 + 3] = fmaf(wb, a3 + b3, yac[g][n8 * 4 + 3]);
                }
            }
        }

        // ---- y fragments -> smem (reuse nbsh) ----
        #pragma unroll
        for (int g = 0; g < 2; g++)
            #pragma unroll
            for (int n8 = 0; n8 < 4; n8++) {
                int r0 = g * 16 + (lane >> 2);
                int c  = n8 * 8 + (lane & 3) * 2;
                *reinterpret_cast<float2*>(&nbsh[r0 * NB_STRIDE + c]) =
                    make_float2(yac[g][n8 * 4 + 0], yac[g][n8 * 4 + 1]);
                *reinterpret_cast<float2*>(&nbsh[(r0 + 8) * NB_STRIDE + c]) =
                    make_float2(yac[g][n8 * 4 + 2], yac[g][n8 * 4 + 3]);
            }
        __syncwarp();

        // ---- scatter-add via vector red: 8 lanes x v4.f32 per edge, 4 edges/iter ----
        #pragma unroll 1
        for (int rr = 0; rr < 8; rr++) {
            int el = rr * 4 + (lane >> 3);
            int c  = (lane & 7) * 4;
            int d  = dstw[el];
            if (d >= 0) {
                float4 v = *reinterpret_cast<const float4*>(&nbsh[el * NB_STRIDE + c]);
                asm volatile("red.global.add.v4.f32 [%0], {%1,%2,%3,%4};"
                             :: "l"(out + (size_t)d * 32 + c),
                                "f"(v.x), "f"(v.y), "f"(v.z), "f"(v.w)
                             : "memory");
            }
        }
        __syncwarp();  // finish reading nbsh before next tile's staging overwrites it

        t = __shfl_sync(0xFFFFFFFFu, tn_l0, 0);
    }
}

extern "C" void kernel_launch(void* const* d_in, const int* in_sizes, int n_in,
                              void* d_out, int out_size) {
    const float* atom = (const float*)d_in[0];
    const float* bond = (const float*)d_in[1];
    const int*   pair = (const int*)d_in[2];
    const float* Kmat = (const float*)d_in[3];
    const float* bias = (const float*)d_in[4];
    float*       out  = (float*)d_out;

    const int n_edges  = in_sizes[1] / 16;
    const int n_wtiles = (n_edges + 31) / 32;

    cudaFuncSetAttribute(edge_network_hmma,
                         cudaFuncAttributeMaxDynamicSharedMemorySize, SMEM_BYTES);

    // reset the work-stealing counter + zero the poisoned output (both capturable)
    void* ctr_addr = nullptr;
    cudaGetSymbolAddress(&ctr_addr, g_tile_ctr);
    cudaMemsetAsync(ctr_addr, 0, sizeof(unsigned int), 0);
    cudaMemsetAsync(d_out, 0, (size_t)out_size * sizeof(float), 0);

    int nblocks = (n_wtiles + NWARPS - 1) / NWARPS;
    if (nblocks > GRID_X) nblocks = GRID_X;
    edge_network_hmma<<<nblocks, NTH, SMEM_BYTES>>>(atom, bond, pair, Kmat, bias, out,
                                                    n_edges, n_wtiles);
}

// round 13
// speedup vs baseline: 1.9465x; 1.4134x over previous
#include <cuda_runtime.h>
#include <cuda_fp16.h>
#include <stdint.h>

// EdgeNetwork via register-fragment fp16 mma.sync, single-pass + work stealing.
//
//   B'[n][k], n in [0,544): n<512 -> B'[n][k] = Kmat[n*32+k]   (reshape(K,512,32))
//                           n>=512 -> bias[(n-512)*32+k]       (reshape(bias,32,32))
//   Per edge e: y[e,i] = sum_{blk=0..16} w[e,blk] * sum_j nb[e,j] * B'[blk*32+i][j]
//   w[e,blk] = bond[e,blk] (blk<16), 1.0 (blk=16, bias block).
//   out = segment_sum(y, src)
//
// Precision: C = f16(A) * f16(B), fp32 accumulate. Residual error = A-residual +
// B-residual, each ~2^-11; B-only was measured 2.19e-4 (R12), so total ~3.1e-4
// (< 1e-3 gate with 3x margin). 272 MMAs/tile — the useful-math minimum.

#define NTH    512
#define NWARPS 16
#define GRID_X 148
#define NBLK   17

#define BF_BYTES  (NBLK * 4 * 2 * 32 * 8)   // 34816: Bfrag[blk][n8][v][lane] uint2
#define NB_STRIDE 36                        // f32 row stride (144B, 16B-aligned rows)
#define NB_BYTES  (32 * NB_STRIDE * 4)      // 4608 per warp (nb staging, reused for y)
#define BD_STRIDE 20                        // f32 row stride (80B, 16B-aligned rows)
#define BD_BYTES  (32 * BD_STRIDE * 4)      // 2560 per warp
#define DST_BYTES (32 * 4)

#define OFF_NB(wid)  (BF_BYTES + (wid) * NB_BYTES)
#define OFF_BD(wid)  (BF_BYTES + NWARPS * NB_BYTES + (wid) * BD_BYTES)
#define OFF_DS(wid)  (BF_BYTES + NWARPS * (NB_BYTES + BD_BYTES) + (wid) * DST_BYTES)
#define SMEM_BYTES   (BF_BYTES + NWARPS * (NB_BYTES + BD_BYTES + DST_BYTES))  // 151552

__device__ unsigned int g_tile_ctr;

// pack {f16(lo_val) in low 16, f16(hi_val) in high 16} with one instruction
__device__ __forceinline__ uint32_t pack_f16x2(float lo_val, float hi_val) {
    uint32_t r;
    asm("cvt.rn.f16x2.f32 %0, %1, %2;" : "=r"(r) : "f"(hi_val), "f"(lo_val));
    return r;
}

#define MMA16816(c0, c1, c2, c3, a0, a1, a2, a3, b0, b1)                        \
    asm volatile(                                                               \
        "mma.sync.aligned.m16n8k16.row.col.f32.f16.f16.f32 "                    \
        "{%0,%1,%2,%3}, {%4,%5,%6,%7}, {%8,%9}, {%0,%1,%2,%3};"                 \
        : "+f"(c0), "+f"(c1), "+f"(c2), "+f"(c3)                                \
        : "r"(a0), "r"(a1), "r"(a2), "r"(a3), "r"(b0), "r"(b1))

__global__ __launch_bounds__(NTH)
void edge_network_hmma(const float* __restrict__ atom,
                       const float* __restrict__ bond,
                       const int* __restrict__ pair,
                       const float* __restrict__ Kmat,
                       const float* __restrict__ bias,
                       float* __restrict__ out,
                       int n_edges, int n_wtiles)
{
    extern __shared__ __align__(16) char smem[];
    const int tid = threadIdx.x;
    const int w = tid >> 5, lane = tid & 31;

    // ---- one-time: build fp16 B fragment table in m16n8k16 B-operand order ----
    // idx = blk*256 + n8*64 + v*32 + lane;  v: 0 = k0-15, 1 = k16-31
    for (int idx = tid; idx < NBLK * 256; idx += NTH) {
        int li  = idx & 31;
        int v   = (idx >> 5) & 1;
        int n8  = (idx >> 6) & 3;
        int blk = idx >> 8;
        int n   = blk * 32 + n8 * 8 + (li >> 2);
        int kb  = v * 16 + (li & 3) * 2;
        const float* src = (n < 512) ? (Kmat + n * 32) : (bias + (n - 512) * 32);
        uint2 r;
        r.x = pack_f16x2(src[kb],     src[kb + 1]);
        r.y = pack_f16x2(src[kb + 8], src[kb + 9]);
        reinterpret_cast<uint2*>(smem)[idx] = r;
    }
    __syncthreads();

    float* nbsh  = (float*)(smem + OFF_NB(w));  // [32][36], reused as y-tile
    float* bdsh  = (float*)(smem + OFF_BD(w));  // [32][20], col 16 = 1.0 (bias weight)
    int*   dstw  = (int*)(smem + OFF_DS(w));
    const uint2* bft = reinterpret_cast<const uint2*>(smem);

    // ---- dynamic work stealing: lane 0 grabs tile indices ----
    int t;
    if (lane == 0) t = (int)atomicAdd(&g_tile_ctr, 1u);
    t = __shfl_sync(0xFFFFFFFFu, t, 0);

    while (t < n_wtiles) {
        int tn_l0;  // grab next tile now; ATOMG latency hides under this tile's work
        if (lane == 0) tn_l0 = (int)atomicAdd(&g_tile_ctr, 1u);

        const int e0 = t * 32;

        // ---- stage: 32 nb rows (gather) + bond rows; 2 lanes per edge, 2 passes ----
        #pragma unroll
        for (int p = 0; p < 2; p++) {
            int el = p * 16 + (lane >> 1);
            int e  = e0 + el;
            int hf = lane & 1;
            const float4 z = make_float4(0.f, 0.f, 0.f, 0.f);
            const float* asrc = nullptr;
            if (e < n_edges) asrc = atom + (size_t)pair[2 * e + 1] * 32 + hf * 16;
            #pragma unroll
            for (int q = 0; q < 4; q++) {
                float4 vv = asrc ? *reinterpret_cast<const float4*>(asrc + q * 4) : z;
                *reinterpret_cast<float4*>(&nbsh[el * NB_STRIDE + hf * 16 + q * 4]) = vv;
            }
            #pragma unroll
            for (int q = 0; q < 2; q++) {
                float4 vv = (e < n_edges)
                    ? *reinterpret_cast<const float4*>(bond + (size_t)e * 16 + hf * 8 + q * 4) : z;
                *reinterpret_cast<float4*>(&bdsh[el * BD_STRIDE + hf * 8 + q * 4]) = vv;
            }
        }
        {
            int e = e0 + lane;
            dstw[lane] = (e < n_edges) ? pair[2 * e] : -1;
            bdsh[lane * BD_STRIDE + 16] = 1.0f;  // bias-block weight
        }
        __syncwarp();

        // ---- build A fragments (fp16, single precision pass) ----
        uint32_t ahi[2][8];
        #pragma unroll
        for (int g = 0; g < 2; g++)
            #pragma unroll
            for (int kc = 0; kc < 2; kc++)
                #pragma unroll
                for (int q = 0; q < 4; q++) {
                    int r = g * 16 + (lane >> 2) + (q & 1) * 8;
                    int c = kc * 16 + (lane & 3) * 2 + (q >> 1) * 8;
                    float2 f = *reinterpret_cast<const float2*>(&nbsh[r * NB_STRIDE + c]);
                    ahi[g][kc * 4 + q] = pack_f16x2(f.x, f.y);
                }
        __syncwarp();  // all lanes done reading nbsh; safe to reuse it for y

        float yac[2][16];
        #pragma unroll
        for (int g = 0; g < 2; g++)
            #pragma unroll
            for (int i = 0; i < 16; i++) yac[g][i] = 0.f;

        // ---- main loop: 17 column-blocks; per block 16 MMAs (one depth-2 chain/group) ----
        #pragma unroll 1
        for (int blk = 0; blk < NBLK; blk++) {
            float w00 = bdsh[((lane >> 2) + 0)  * BD_STRIDE + blk];
            float w01 = bdsh[((lane >> 2) + 8)  * BD_STRIDE + blk];
            float w10 = bdsh[((lane >> 2) + 16) * BD_STRIDE + blk];
            float w11 = bdsh[((lane >> 2) + 24) * BD_STRIDE + blk];
            #pragma unroll
            for (int n8 = 0; n8 < 4; n8++) {
                const uint2* bp = bft + ((blk * 4 + n8) * 2) * 32 + lane;
                uint2 v0 = bp[0], v1 = bp[32];
                #pragma unroll
                for (int g = 0; g < 2; g++) {
                    float c0 = 0.f, c1 = 0.f, c2 = 0.f, c3 = 0.f;
                    MMA16816(c0, c1, c2, c3, ahi[g][0], ahi[g][1], ahi[g][2], ahi[g][3], v0.x, v0.y);
                    MMA16816(c0, c1, c2, c3, ahi[g][4], ahi[g][5], ahi[g][6], ahi[g][7], v1.x, v1.y);
                    float wa = g ? w10 : w00;
                    float wb = g ? w11 : w01;
                    yac[g][n8 * 4 + 0] = fmaf(wa, c0, yac[g][n8 * 4 + 0]);
                    yac[g][n8 * 4 + 1] = fmaf(wa, c1, yac[g][n8 * 4 + 1]);
                    yac[g][n8 * 4 + 2] = fmaf(wb, c2, yac[g][n8 * 4 + 2]);
                    yac[g][n8 * 4 + 3] = fmaf(wb, c3, yac[g][n8 * 4 + 3]);
                }
            }
        }

        // ---- y fragments -> smem (reuse nbsh) ----
        #pragma unroll
        for (int g = 0; g < 2; g++)
            #pragma unroll
            for (int n8 = 0; n8 < 4; n8++) {
                int r0 = g * 16 + (lane >> 2);
                int c  = n8 * 8 + (lane & 3) * 2;
                *reinterpret_cast<float2*>(&nbsh[r0 * NB_STRIDE + c]) =
                    make_float2(yac[g][n8 * 4 + 0], yac[g][n8 * 4 + 1]);
                *reinterpret_cast<float2*>(&nbsh[(r0 + 8) * NB_STRIDE + c]) =
                    make_float2(yac[g][n8 * 4 + 2], yac[g][n8 * 4 + 3]);
            }
        __syncwarp();

        // ---- scatter-add via vector red: 8 lanes x v4.f32 per edge, 4 edges/iter ----
        #pragma unroll 1
        for (int rr = 0; rr < 8; rr++) {
            int el = rr * 4 + (lane >> 3);
            int c  = (lane & 7) * 4;
            int d  = dstw[el];
            if (d >= 0) {
                float4 v = *reinterpret_cast<const float4*>(&nbsh[el * NB_STRIDE + c]);
                asm volatile("red.global.add.v4.f32 [%0], {%1,%2,%3,%4};"
                             :: "l"(out + (size_t)d * 32 + c),
                                "f"(v.x), "f"(v.y), "f"(v.z), "f"(v.w)
                             : "memory");
            }
        }
        __syncwarp();  // finish reading nbsh before next tile's staging overwrites it

        t = __shfl_sync(0xFFFFFFFFu, tn_l0, 0);
    }
}

extern "C" void kernel_launch(void* const* d_in, const int* in_sizes, int n_in,
                              void* d_out, int out_size) {
    const float* atom = (const float*)d_in[0];
    const float* bond = (const float*)d_in[1];
    const int*   pair = (const int*)d_in[2];
    const float* Kmat = (const float*)d_in[3];
    const float* bias = (const float*)d_in[4];
    float*       out  = (float*)d_out;

    const int n_edges  = in_sizes[1] / 16;
    const int n_wtiles = (n_edges + 31) / 32;

    cudaFuncSetAttribute(edge_network_hmma,
                         cudaFuncAttributeMaxDynamicSharedMemorySize, SMEM_BYTES);

    // reset the work-stealing counter + zero the poisoned output (both capturable)
    void* ctr_addr = nullptr;
    cudaGetSymbolAddress(&ctr_addr, g_tile_ctr);
    cudaMemsetAsync(ctr_addr, 0, sizeof(unsigned int), 0);
    cudaMemsetAsync(d_out, 0, (size_t)out_size * sizeof(float), 0);

    int nblocks = (n_wtiles + NWARPS - 1) / NWARPS;
    if (nblocks > GRID_X) nblocks = GRID_X;
    edge_network_hmma<<<nblocks, NTH, SMEM_BYTES>>>(atom, bond, pair, Kmat, bias, out,
                                                    n_edges, n_wtiles);
}